// round 17
// baseline (speedup 1.0000x reference)
#include <cuda_runtime.h>
#include <cuda_bf16.h>
#include <cstdint>

// ---------------- problem constants ----------------
#define D_MODEL   256
#define N_HEADS   8
#define HEAD_DIM  32
#define N_LEVELS  4
#define N_POINTS  4
#define D_FFN     1024
#define HW        128
#define LQ        (HW * HW)            // 16384
#define LIN       (N_LEVELS * LQ)      // 65536
#define BATCH     2
#define ROWS_Q    (BATCH * LQ)         // 32768
#define ROWS_V    (BATCH * LIN)        // 131072

// ---------------- scratch (device globals) ---------------------------------
__device__ __align__(256) __nv_bfloat16 sc_value[ROWS_V * D_MODEL]; // head-major
__device__ __align__(256) float         sc_off  [ROWS_Q * D_MODEL];
__device__ __align__(256) float         sc_attn [ROWS_Q * 128];
__device__ __align__(256) __nv_bfloat16 sc_samp [ROWS_Q * D_MODEL];
__device__ __align__(256) float         sc_src2 [ROWS_Q * D_MODEL];
__device__ __align__(256) float         sc_src  [ROWS_Q * D_MODEL];
__device__ __align__(256) __nv_bfloat16 sc_srcb [ROWS_Q * D_MODEL];
__device__ __align__(256) __nv_bfloat16 sc_ffnb [ROWS_Q * D_FFN];
__device__ __align__(256) float         sc_ffn2 [ROWS_Q * D_MODEL];
// bf16 transposed weights Wt[n][k]
__device__ __align__(256) __nv_bfloat16 sc_wvalT[D_MODEL * D_MODEL];
__device__ __align__(256) __nv_bfloat16 sc_wqT  [384 * D_MODEL];      // off(256)+attn(128)
__device__ __align__(256) __nv_bfloat16 sc_woutT[D_MODEL * D_MODEL];
__device__ __align__(256) __nv_bfloat16 sc_w1T  [D_FFN * D_MODEL];
__device__ __align__(256) __nv_bfloat16 sc_w2T  [D_MODEL * D_FFN];
__device__ __align__(256) float         sc_bq   [384];                // b_off ++ b_attn

// ---------------- helpers --------------------------------------------------
__device__ __forceinline__ void mma_bf16(float c[4], const uint32_t a[4],
                                         const uint32_t b[2]) {
    asm volatile(
        "mma.sync.aligned.m16n8k16.row.col.f32.bf16.bf16.f32 "
        "{%0,%1,%2,%3}, {%4,%5,%6,%7}, {%8,%9}, {%0,%1,%2,%3};"
        : "+f"(c[0]), "+f"(c[1]), "+f"(c[2]), "+f"(c[3])
        : "r"(a[0]), "r"(a[1]), "r"(a[2]), "r"(a[3]), "r"(b[0]), "r"(b[1]));
}
__device__ __forceinline__ void cp_async16(void* smem, const void* gmem) {
    const uint32_t s = (uint32_t)__cvta_generic_to_shared(smem);
    asm volatile("cp.async.ca.shared.global [%0], [%1], 16;\n" :: "r"(s), "l"(gmem));
}
__device__ __forceinline__ void cp_commit() {
    asm volatile("cp.async.commit_group;\n");
}
template <int N>
__device__ __forceinline__ void cp_wait() {
    asm volatile("cp.async.wait_group %0;\n" :: "n"(N));
}
__device__ __forceinline__ uint32_t packbf(float x, float y) {
    __nv_bfloat162 p = __floats2bfloat162_rn(x, y);
    return *(uint32_t*)&p;
}
__device__ __forceinline__ uint64_t bf2f32x2(uint32_t u) {
    const uint32_t lo = u << 16, hi = u & 0xffff0000u;
    uint64_t d;
    asm("mov.b64 %0, {%1,%2};" : "=l"(d) : "r"(lo), "r"(hi));
    return d;
}
__device__ __forceinline__ uint64_t bcastf2(float a) {
    uint64_t d;
    asm("mov.b64 %0, {%1,%1};" : "=l"(d) : "f"(a));
    return d;
}
__device__ __forceinline__ void fma2(uint64_t& acc, uint64_t v, uint64_t w) {
    asm("fma.rn.f32x2 %0, %1, %2, %0;" : "+l"(acc) : "l"(v), "l"(w));
}

#define BPAD 40   // bf16 row stride (BK=32 tiles): conflict-free LDSM phases

// ---- warp-tile compute (64x32) on one smem stage ---------------------------
template <int PITCH, int BK>
__device__ __forceinline__ void gemm_compute_stage(
    const __nv_bfloat16* As, const __nv_bfloat16* Bs,
    float acc[4][4][4], int wm, int wn, int lane)
{
    const uint32_t aOff = (uint32_t)__cvta_generic_to_shared(As) +
        (uint32_t)(((wm + (lane & 15)) * PITCH + (lane >> 4) * 8) * 2);
    const uint32_t bOff = (uint32_t)__cvta_generic_to_shared(Bs) +
        (uint32_t)(((wn + (lane & 7) + (lane >> 4) * 8) * PITCH
                    + ((lane >> 3) & 1) * 8) * 2);

    #pragma unroll
    for (int ks = 0; ks < BK; ks += 16) {
        uint32_t af[4][4];
        #pragma unroll
        for (int mt = 0; mt < 4; ++mt)
            asm volatile(
                "ldmatrix.sync.aligned.m8n8.x4.shared.b16 {%0,%1,%2,%3}, [%4];"
                : "=r"(af[mt][0]), "=r"(af[mt][1]), "=r"(af[mt][2]), "=r"(af[mt][3])
                : "r"(aOff + (uint32_t)((mt * 16 * PITCH + ks) * 2)));
        uint32_t bf[4][2];
        #pragma unroll
        for (int np = 0; np < 2; ++np)
            asm volatile(
                "ldmatrix.sync.aligned.m8n8.x4.shared.b16 {%0,%1,%2,%3}, [%4];"
                : "=r"(bf[2*np][0]), "=r"(bf[2*np][1]),
                  "=r"(bf[2*np+1][0]), "=r"(bf[2*np+1][1])
                : "r"(bOff + (uint32_t)((np * 16 * PITCH + ks) * 2)));
        #pragma unroll
        for (int mt = 0; mt < 4; ++mt)
            #pragma unroll
            for (int nt = 0; nt < 4; ++nt)
                mma_bf16(acc[mt][nt], af[mt], bf[nt]);
    }
}

// ================= GEMM 1: value projection (128x128) =======================
__global__ __launch_bounds__(256)
void bgemm_value(const float* __restrict__ A, const float* __restrict__ A2,
                 const __nv_bfloat16* __restrict__ Bt, const float* __restrict__ bias,
                 __nv_bfloat16* __restrict__ Cb, int K)
{
    __shared__ __align__(16) __nv_bfloat16 As[2][128 * BPAD];
    __shared__ __align__(16) __nv_bfloat16 Bs[2][128 * BPAD];

    const int tid  = threadIdx.x;
    const int wid  = tid >> 5;
    const int lane = tid & 31;
    const int g    = lane >> 2;
    const int t    = lane & 3;
    const int bm = blockIdx.y * 128;
    const int bn = blockIdx.x * 128;
    const int wm = (wid & 1) * 64;
    const int wn = (wid >> 1) * 32;

    const int la_r = tid >> 1;
    const int la_c = (tid & 1) * 16;
    const float* a_ptr  = A  + (size_t)(bm + la_r) * K + la_c;
    const float* a2_ptr = A2 + (size_t)(bm + la_r) * K + la_c;

    const int nk = K / 32;

    auto ldgA = [&](int i, uint32_t v[8]) {
        const int k0 = i * 32;
        #pragma unroll
        for (int j = 0; j < 4; ++j) {
            float4 a = *(const float4*)(a_ptr + k0 + j * 4);
            const float4 b = *(const float4*)(a2_ptr + k0 + j * 4);
            a.x += b.x; a.y += b.y; a.z += b.z; a.w += b.w;
            v[2 * j]     = packbf(a.x, a.y);
            v[2 * j + 1] = packbf(a.z, a.w);
        }
    };
    auto stsA = [&](int s, const uint32_t v[8]) {
        uint32_t* p = (uint32_t*)&As[s][la_r * BPAD + la_c];
        *(uint4*)p       = make_uint4(v[0], v[1], v[2], v[3]);
        *(uint4*)(p + 4) = make_uint4(v[4], v[5], v[6], v[7]);
    };
    auto cpB = [&](int s, int i) {
        const int k0 = i * 32;
        #pragma unroll
        for (int j = 0; j < 2; ++j) {
            const int ch = j * 256 + tid;
            const int r  = ch >> 2;
            const int cc = (ch & 3) * 8;
            cp_async16(&Bs[s][r * BPAD + cc], Bt + (size_t)(bn + r) * K + k0 + cc);
        }
    };

    float acc[4][4][4] = {};
    uint32_t rA[8];

    ldgA(0, rA); stsA(0, rA); cpB(0, 0); cp_commit();
    ldgA(1, rA);

    for (int i = 0; i < nk; ++i) {
        cp_wait<0>();
        __syncthreads();
        if (i + 1 < nk) { stsA((i + 1) & 1, rA); cpB((i + 1) & 1, i + 1); cp_commit(); }
        if (i + 2 < nk) ldgA(i + 2, rA);
        gemm_compute_stage<BPAD, 32>(As[i & 1], Bs[i & 1], acc, wm, wn, lane);
    }

    // epilogue: head-major store
    const int nb  = bm / LIN;
    const int pix0 = bm & (LIN - 1);
    #pragma unroll
    for (int nt = 0; nt < 4; ++nt) {
        const int n = bn + wn + nt * 8 + t * 2;
        const int h = n >> 5, c = n & 31;
        const float bx = bias[n], by = bias[n + 1];
        __nv_bfloat16* hb = Cb + ((size_t)(nb * 8 + h) * LIN) * 32 + c;
        #pragma unroll
        for (int mt = 0; mt < 4; ++mt) {
            const int pix = pix0 + wm + mt * 16 + g;
            *(uint32_t*)&hb[(size_t)pix * 32] =
                packbf(acc[mt][nt][0] + bx, acc[mt][nt][1] + by);
            *(uint32_t*)&hb[(size_t)(pix + 8) * 32] =
                packbf(acc[mt][nt][2] + bx, acc[mt][nt][3] + by);
        }
    }
}

// ================= GEMM 2: fused q-add + off/attn split (128x128) ===========
__global__ __launch_bounds__(256)
void bgemm_qa(const float* __restrict__ A, const float* __restrict__ A2,
              const __nv_bfloat16* __restrict__ Bt, const float* __restrict__ bias,
              float* __restrict__ Coff, float* __restrict__ Cattn)
{
    const int K = 256;
    __shared__ __align__(16) __nv_bfloat16 As[2][128 * BPAD];
    __shared__ __align__(16) __nv_bfloat16 Bs[2][128 * BPAD];

    const int tid  = threadIdx.x;
    const int wid  = tid >> 5;
    const int lane = tid & 31;
    const int g    = lane >> 2;
    const int t    = lane & 3;
    const int bm = blockIdx.y * 128;
    const int bn = blockIdx.x * 128;
    const int wm = (wid & 1) * 64;
    const int wn = (wid >> 1) * 32;

    const int la_r = tid >> 1;
    const int la_c = (tid & 1) * 16;
    const int r_glob = bm + la_r;
    const int pos_row = r_glob + 49152 * ((r_glob >> 14) + 1);
    const float* a_ptr  = A  + (size_t)r_glob * K + la_c;
    const float* a2_ptr = A2 + (size_t)pos_row * K + la_c;

    const int nk = K / 32;

    auto ldgA = [&](int i, uint32_t v[8]) {
        const int k0 = i * 32;
        #pragma unroll
        for (int j = 0; j < 4; ++j) {
            float4 a = *(const float4*)(a_ptr + k0 + j * 4);
            const float4 b = *(const float4*)(a2_ptr + k0 + j * 4);
            a.x += b.x; a.y += b.y; a.z += b.z; a.w += b.w;
            v[2 * j]     = packbf(a.x, a.y);
            v[2 * j + 1] = packbf(a.z, a.w);
        }
    };
    auto stsA = [&](int s, const uint32_t v[8]) {
        uint32_t* p = (uint32_t*)&As[s][la_r * BPAD + la_c];
        *(uint4*)p       = make_uint4(v[0], v[1], v[2], v[3]);
        *(uint4*)(p + 4) = make_uint4(v[4], v[5], v[6], v[7]);
    };
    auto cpB = [&](int s, int i) {
        const int k0 = i * 32;
        #pragma unroll
        for (int j = 0; j < 2; ++j) {
            const int ch = j * 256 + tid;
            const int r  = ch >> 2;
            const int cc = (ch & 3) * 8;
            cp_async16(&Bs[s][r * BPAD + cc], Bt + (size_t)(bn + r) * K + k0 + cc);
        }
    };

    float acc[4][4][4] = {};
    uint32_t rA[8];

    ldgA(0, rA); stsA(0, rA); cpB(0, 0); cp_commit();
    ldgA(1, rA);

    for (int i = 0; i < nk; ++i) {
        cp_wait<0>();
        __syncthreads();
        if (i + 1 < nk) { stsA((i + 1) & 1, rA); cpB((i + 1) & 1, i + 1); cp_commit(); }
        if (i + 2 < nk) ldgA(i + 2, rA);
        gemm_compute_stage<BPAD, 32>(As[i & 1], Bs[i & 1], acc, wm, wn, lane);
    }

    const bool is_attn = (bn >= 256);
    float* C = is_attn ? Cattn : Coff;
    const int stride = is_attn ? 128 : 256;
    const int cbase  = is_attn ? bn - 256 : bn;
    #pragma unroll
    for (int nt = 0; nt < 4; ++nt) {
        const int nn = wn + nt * 8 + t * 2;
        const float bx = bias[bn + nn], by = bias[bn + nn + 1];
        #pragma unroll
        for (int mt = 0; mt < 4; ++mt) {
            const int m = bm + wm + mt * 16 + g;
            *(float2*)&C[(size_t)m * stride + cbase + nn] =
                make_float2(acc[mt][nt][0] + bx, acc[mt][nt][1] + by);
            *(float2*)&C[(size_t)(m + 8) * stride + cbase + nn] =
                make_float2(acc[mt][nt][2] + bx, acc[mt][nt][3] + by);
        }
    }
}

// ================= GEMM 3 (wide): bf16 A, CTA 128x256, warp 64x64 ==========
// BK=32, 2-stage. Optional fused residual. N % 256 == 0.
template <bool RELU, bool BF16_OUT, bool RESID>
__global__ __launch_bounds__(256)
void bgemm_wide(const __nv_bfloat16* __restrict__ A,
                const __nv_bfloat16* __restrict__ Bt, const float* __restrict__ bias,
                const float* __restrict__ Res,
                float* __restrict__ C, __nv_bfloat16* __restrict__ Cb,
                int M, int N, int K)
{
    __shared__ __align__(16) __nv_bfloat16 As[2][128 * BPAD];
    __shared__ __align__(16) __nv_bfloat16 Bs[2][256 * BPAD];

    const int tid  = threadIdx.x;
    const int wid  = tid >> 5;
    const int lane = tid & 31;
    const int g    = lane >> 2;
    const int t    = lane & 3;
    const int bm = blockIdx.y * 128;
    const int bn = blockIdx.x * 256;
    const int wm = (wid & 1) * 64;
    const int wn = (wid >> 1) * 64;

    const int nk = K / 32;

    auto load_stage = [&](int s, int i) {
        const int k0 = i * 32;
        // A: 128x32 bf16 = 512 16B chunks
        #pragma unroll
        for (int j = 0; j < 2; ++j) {
            const int ch = j * 256 + tid;
            const int r  = ch >> 2;
            const int cc = (ch & 3) * 8;
            cp_async16(&As[s][r * BPAD + cc], A + (size_t)(bm + r) * K + k0 + cc);
        }
        // B: 256x32 bf16 = 1024 16B chunks
        #pragma unroll
        for (int j = 0; j < 4; ++j) {
            const int ch = j * 256 + tid;
            const int r  = ch >> 2;
            const int cc = (ch & 3) * 8;
            cp_async16(&Bs[s][r * BPAD + cc], Bt + (size_t)(bn + r) * K + k0 + cc);
        }
    };

    float acc[4][8][4] = {};   // [mt][nt][reg]

    load_stage(0, 0); cp_commit();

    const uint32_t aBase = (uint32_t)__cvta_generic_to_shared(As) +
        (uint32_t)(((wm + (lane & 15)) * BPAD + (lane >> 4) * 8) * 2);
    const uint32_t bBase = (uint32_t)__cvta_generic_to_shared(Bs) +
        (uint32_t)(((wn + (lane & 7) + (lane >> 4) * 8) * BPAD
                    + ((lane >> 3) & 1) * 8) * 2);
    const uint32_t stageA = 128 * BPAD * 2;  // bytes
    const uint32_t stageB = 256 * BPAD * 2;

    for (int i = 0; i < nk; ++i) {
        cp_wait<0>();
        __syncthreads();
        if (i + 1 < nk) { load_stage((i + 1) & 1, i + 1); cp_commit(); }

        const uint32_t aOff = aBase + (i & 1) * stageA;
        const uint32_t bOff = bBase + (i & 1) * stageB;
        #pragma unroll
        for (int ks = 0; ks < 32; ks += 16) {
            uint32_t af[4][4];
            #pragma unroll
            for (int mt = 0; mt < 4; ++mt)
                asm volatile(
                    "ldmatrix.sync.aligned.m8n8.x4.shared.b16 {%0,%1,%2,%3}, [%4];"
                    : "=r"(af[mt][0]), "=r"(af[mt][1]), "=r"(af[mt][2]), "=r"(af[mt][3])
                    : "r"(aOff + (uint32_t)((mt * 16 * BPAD + ks) * 2)));
            uint32_t bf[8][2];
            #pragma unroll
            for (int np = 0; np < 4; ++np)
                asm volatile(
                    "ldmatrix.sync.aligned.m8n8.x4.shared.b16 {%0,%1,%2,%3}, [%4];"
                    : "=r"(bf[2*np][0]), "=r"(bf[2*np][1]),
                      "=r"(bf[2*np+1][0]), "=r"(bf[2*np+1][1])
                    : "r"(bOff + (uint32_t)((np * 16 * BPAD + ks) * 2)));
            #pragma unroll
            for (int mt = 0; mt < 4; ++mt)
                #pragma unroll
                for (int nt = 0; nt < 8; ++nt)
                    mma_bf16(acc[mt][nt], af[mt], bf[nt]);
        }
    }

    #pragma unroll
    for (int nt = 0; nt < 8; ++nt) {
        const int n = bn + wn + nt * 8 + t * 2;
        const float bx = bias[n], by = bias[n + 1];
        #pragma unroll
        for (int mt = 0; mt < 4; ++mt) {
            const int m = bm + wm + mt * 16 + g;
            float2 v0 = { acc[mt][nt][0] + bx, acc[mt][nt][1] + by };
            float2 v1 = { acc[mt][nt][2] + bx, acc[mt][nt][3] + by };
            if (RESID) {
                const float2 r0 = *(const float2*)&Res[(size_t)m * N + n];
                const float2 r1 = *(const float2*)&Res[(size_t)(m + 8) * N + n];
                v0.x += r0.x; v0.y += r0.y;
                v1.x += r1.x; v1.y += r1.y;
            }
            if (RELU) {
                v0.x = fmaxf(v0.x, 0.f); v0.y = fmaxf(v0.y, 0.f);
                v1.x = fmaxf(v1.x, 0.f); v1.y = fmaxf(v1.y, 0.f);
            }
            if (BF16_OUT) {
                *(uint32_t*)&Cb[(size_t)m * N + n]       = packbf(v0.x, v0.y);
                *(uint32_t*)&Cb[(size_t)(m + 8) * N + n] = packbf(v1.x, v1.y);
            } else {
                *(float2*)&C[(size_t)m * N + n]       = v0;
                *(float2*)&C[(size_t)(m + 8) * N + n] = v1;
            }
        }
    }
}

// ================= single prep kernel: all transposes + bias concat =========
__device__ __forceinline__ void do_transpose_tile(
    const float* W, __nv_bfloat16* Wt, int K, int N, int tilesX, int local)
{
    __shared__ float tt[32][33];
    const int bx = (local % tilesX) * 32;
    const int by = (local / tilesX) * 32;
    const int x = threadIdx.x, y = threadIdx.y;
    #pragma unroll
    for (int j = 0; j < 32; j += 8)
        tt[y + j][x] = W[(size_t)(by + y + j) * N + bx + x];
    __syncthreads();
    #pragma unroll
    for (int j = 0; j < 32; j += 8)
        Wt[(size_t)(bx + y + j) * K + by + x] = __float2bfloat16_rn(tt[x][y + j]);
}

__global__ void prep_kernel(
    const float* __restrict__ W_val, const float* __restrict__ W_off,
    const float* __restrict__ W_attn, const float* __restrict__ W_out,
    const float* __restrict__ W1, const float* __restrict__ W2,
    const float* __restrict__ b_off, const float* __restrict__ b_attn,
    __nv_bfloat16* __restrict__ wvalT, __nv_bfloat16* __restrict__ wqT,
    __nv_bfloat16* __restrict__ woutT, __nv_bfloat16* __restrict__ w1T,
    __nv_bfloat16* __restrict__ w2T, float* __restrict__ bq)
{
    const int b = blockIdx.x;
    if      (b < 64)  do_transpose_tile(W_val,  wvalT,           256, 256,  8,  b);
    else if (b < 128) do_transpose_tile(W_off,  wqT,             256, 256,  8,  b - 64);
    else if (b < 160) do_transpose_tile(W_attn, wqT + 256 * 256, 256, 128,  4,  b - 128);
    else if (b < 224) do_transpose_tile(W_out,  woutT,           256, 256,  8,  b - 160);
    else if (b < 480) do_transpose_tile(W1,     w1T,             256, 1024, 32, b - 224);
    else if (b < 736) do_transpose_tile(W2,     w2T,            1024, 256,  8,  b - 480);
    else {
        const int t = threadIdx.y * 32 + threadIdx.x;
        bq[t] = b_off[t];
        if (t < 128) bq[256 + t] = b_attn[t];
    }
}

// ---------------- fused softmax + deformable bilinear sampling --------------
__global__ __launch_bounds__(256)
void sample_kernel(const float* __restrict__ off, const float* __restrict__ attn,
                   const float* __restrict__ ref,
                   const __nv_bfloat16* __restrict__ value,
                   __nv_bfloat16* __restrict__ out)
{
    const int tw  = blockIdx.x * 16 + (threadIdx.x >> 4);
    const int l16 = threadIdx.x & 15;
    const int h = tw & 7;
    const int q = (tw >> 3) & (LQ - 1);
    const int n = tw >> 17;
    const size_t row = (size_t)n * LQ + q;

    const int p  = l16;
    const int lv = p >> 2;

    const float logit = attn[row * 128 + h * 16 + p];
    float mx = logit;
    #pragma unroll
    for (int o = 8; o; o >>= 1) mx = fmaxf(mx, __shfl_xor_sync(0xffffffffu, mx, o, 16));
    const float e = __expf(logit - mx);
    float ssum = e;
    #pragma unroll
    for (int o = 8; o; o >>= 1) ssum += __shfl_xor_sync(0xffffffffu, ssum, o, 16);
    const float aw = e * (1.f / ssum);

    const float2 o2 = *(const float2*)&off[row * 256 + h * 32 + 2 * p];
    const float rx = ref[row * 8 + lv * 2];
    const float ry = ref[row * 8 + lv * 2 + 1];
    const float x = fmaf(rx, 128.f, o2.x - 0.5f);
    const float y = fmaf(ry, 128.f, o2.y - 0.5f);
    const float x0f = floorf(x), y0f = floorf(y);
    const float wx = x - x0f, wy = y - y0f;
    const int x0 = (int)x0f, y0 = (int)y0f;

    const float sA = (x0 >= 0 && x0 < HW) ? (1.f - wx) : 0.f;
    const float sB = (x0 >= -1 && x0 < HW - 1) ? wx : 0.f;
    const int   b  = min(max(x0, 0), HW - 2);
    float s0, s1;
    if (x0 >= 0) { s0 = sA; s1 = sB; } else { s0 = sB; s1 = 0.f; }
    if (x0 >= HW - 1) { s0 = 0.f; s1 = sA; }

    const float r0 = (y0 >= 0 && y0 < HW) ? (1.f - wy) : 0.f;
    const float r1 = (y0 >= -1 && y0 < HW - 1) ? wy : 0.f;
    const int y0c = min(max(y0, 0), HW - 1);
    const int y1c = min(max(y0 + 1, 0), HW - 1);

    const float q00 = aw * r0 * s0, q01 = aw * r0 * s1;
    const float q10 = aw * r1 * s0, q11 = aw * r1 * s1;
    const int ipack = ((lv * LQ + y0c * HW + b) * 16) | ((y1c - y0c) << 28);

    const uint32_t* vbw =
        (const uint32_t*)value + ((size_t)(n * 8 + h) * LIN) * 16;
    const int lw = 2 * l16;

    uint64_t acc01 = 0, acc23 = 0;
    #pragma unroll
    for (int pp = 0; pp < 16; ++pp) {
        const int   ip  = __shfl_sync(0xffffffffu, ipack, pp, 16);
        const float b00 = __shfl_sync(0xffffffffu, q00, pp, 16);
        const float b01 = __shfl_sync(0xffffffffu, q01, pp, 16);
        const float b10 = __shfl_sync(0xffffffffu, q10, pp, 16);
        const float b11 = __shfl_sync(0xffffffffu, q11, pp, 16);
        const int ib = ip & 0x0FFFFFFF;
        const int dy = (ip >> 28) << 11;
        const uint64_t wt2 = bcastf2((l16 < 8) ? b00 : b01);
        const uint64_t wb2 = bcastf2((l16 < 8) ? b10 : b11);
        const uint2 v0 = *(const uint2*)(vbw + ib + lw);
        const uint2 v1 = *(const uint2*)(vbw + ib + dy + lw);
        fma2(acc01, bf2f32x2(v0.x), wt2);
        fma2(acc23, bf2f32x2(v0.y), wt2);
        fma2(acc01, bf2f32x2(v1.x), wb2);
        fma2(acc23, bf2f32x2(v1.y), wb2);
    }
    float a0, a1, a2, a3;
    asm("mov.b64 {%0,%1}, %2;" : "=f"(a0), "=f"(a1) : "l"(acc01));
    asm("mov.b64 {%0,%1}, %2;" : "=f"(a2), "=f"(a3) : "l"(acc23));

    a0 += __shfl_xor_sync(0xffffffffu, a0, 8, 16);
    a1 += __shfl_xor_sync(0xffffffffu, a1, 8, 16);
    a2 += __shfl_xor_sync(0xffffffffu, a2, 8, 16);
    a3 += __shfl_xor_sync(0xffffffffu, a3, 8, 16);

    if (l16 < 8) {
        uint2 w = { packbf(a0, a1), packbf(a2, a3) };
        *((uint2*)(out + row * 256 + h * 32) + l16) = w;
    }
}

// ---------------- pure layernorm (input already has residual) ---------------
__global__ __launch_bounds__(256)
void ln_kernel(const float* __restrict__ a,
               const float* __restrict__ gamma, const float* __restrict__ beta,
               float* __restrict__ out, __nv_bfloat16* __restrict__ out_b)
{
    const int row = blockIdx.x;
    const int t = threadIdx.x;
    const size_t idx = (size_t)row * 256 + t;
    const float v = a[idx];

    __shared__ float red[8];
    float s = v;
    #pragma unroll
    for (int o = 16; o; o >>= 1) s += __shfl_xor_sync(0xffffffffu, s, o);
    if ((t & 31) == 0) red[t >> 5] = s;
    __syncthreads();
    float mean = 0.f;
    #pragma unroll
    for (int i = 0; i < 8; ++i) mean += red[i];
    mean *= (1.f / 256.f);
    __syncthreads();

    const float d = v - mean;
    float s2 = d * d;
    #pragma unroll
    for (int o = 16; o; o >>= 1) s2 += __shfl_xor_sync(0xffffffffu, s2, o);
    if ((t & 31) == 0) red[t >> 5] = s2;
    __syncthreads();
    float var = 0.f;
    #pragma unroll
    for (int i = 0; i < 8; ++i) var += red[i];
    var *= (1.f / 256.f);

    const float r = d * rsqrtf(var + 1e-5f) * gamma[t] + beta[t];
    out[idx] = r;
    if (out_b) out_b[idx] = __float2bfloat16_rn(r);
}

// ---------------- launch -----------------------------------------------------
extern "C" void kernel_launch(void* const* d_in, const int* in_sizes, int n_in,
                              void* d_out, int out_size)
{
    (void)in_sizes; (void)n_in; (void)out_size;
    const float* cur_src = (const float*)d_in[0];
    const float* src_all = (const float*)d_in[1];
    const float* pos     = (const float*)d_in[2];
    const float* refpts  = (const float*)d_in[3];
    const float* W_off   = (const float*)d_in[6];
    const float* b_off   = (const float*)d_in[7];
    const float* W_attn  = (const float*)d_in[8];
    const float* b_attn  = (const float*)d_in[9];
    const float* W_val   = (const float*)d_in[10];
    const float* b_val   = (const float*)d_in[11];
    const float* W_out   = (const float*)d_in[12];
    const float* b_out   = (const float*)d_in[13];
    const float* gamma1  = (const float*)d_in[14];
    const float* beta1   = (const float*)d_in[15];
    const float* W1      = (const float*)d_in[16];
    const float* b1      = (const float*)d_in[17];
    const float* W2      = (const float*)d_in[18];
    const float* b2      = (const float*)d_in[19];
    const float* gamma2  = (const float*)d_in[20];
    const float* beta2   = (const float*)d_in[21];
    float* out = (float*)d_out;

    float *g_off, *g_attn, *g_src2, *g_src, *g_ffn2, *g_bq;
    __nv_bfloat16 *g_value, *g_samp, *g_srcb, *g_ffnb;
    __nv_bfloat16 *g_wvalT, *g_wqT, *g_woutT, *g_w1T, *g_w2T;
    cudaGetSymbolAddress((void**)&g_value, sc_value);
    cudaGetSymbolAddress((void**)&g_off,   sc_off);
    cudaGetSymbolAddress((void**)&g_attn,  sc_attn);
    cudaGetSymbolAddress((void**)&g_samp,  sc_samp);
    cudaGetSymbolAddress((void**)&g_src2,  sc_src2);
    cudaGetSymbolAddress((void**)&g_src,   sc_src);
    cudaGetSymbolAddress((void**)&g_srcb,  sc_srcb);
    cudaGetSymbolAddress((void**)&g_ffnb,  sc_ffnb);
    cudaGetSymbolAddress((void**)&g_ffn2,  sc_ffn2);
    cudaGetSymbolAddress((void**)&g_wvalT, sc_wvalT);
    cudaGetSymbolAddress((void**)&g_wqT,   sc_wqT);
    cudaGetSymbolAddress((void**)&g_woutT, sc_woutT);
    cudaGetSymbolAddress((void**)&g_w1T,   sc_w1T);
    cudaGetSymbolAddress((void**)&g_w2T,   sc_w2T);
    cudaGetSymbolAddress((void**)&g_bq,    sc_bq);

    // 0. one prep kernel: all weight transposes + bias concat
    prep_kernel<<<737, dim3(32, 8)>>>(W_val, W_off, W_attn, W_out, W1, W2,
                                      b_off, b_attn,
                                      g_wvalT, g_wqT, g_woutT, g_w1T, g_w2T, g_bq);

    // 1. value = bf16(src_all + pos) @ W_val + b_val -> head-major bf16
    bgemm_value<<<dim3(2, ROWS_V / 128), 256>>>(
        src_all, pos, g_wvalT, b_val, g_value, 256);

    // 2. [off | attn] = (cur_src + pos[:,-1]) @ [W_off|W_attn] + [b_off|b_attn]
    bgemm_qa<<<dim3(3, ROWS_Q / 128), 256>>>(
        cur_src, pos, g_wqT, g_bq, g_off, g_attn);

    // 3. fused softmax + deformable bilinear sampling -> bf16
    sample_kernel<<<(BATCH * LQ * N_HEADS) / 16, 256>>>(
        g_off, g_attn, refpts, g_value, g_samp);

    // 4. src2sum = samp @ W_out + b_out + cur_src  (residual fused, wide)
    bgemm_wide<false, false, true><<<dim3(1, ROWS_Q / 128), 256>>>(
        g_samp, g_woutT, b_out, cur_src, g_src2, nullptr, ROWS_Q, 256, 256);

    // 5. src = LN(src2sum), bf16 twin for FFN1
    ln_kernel<<<ROWS_Q, 256>>>(g_src2, gamma1, beta1, g_src, g_srcb);

    // 6. ffn_h = relu(src @ W1 + b1) -> bf16  (wide)
    bgemm_wide<true, true, false><<<dim3(D_FFN / 256, ROWS_Q / 128), 256>>>(
        g_srcb, g_w1T, b1, nullptr, nullptr, g_ffnb, ROWS_Q, D_FFN, 256);

    // 7. ffn2sum = ffn_h @ W2 + b2 + src  (residual fused, wide)
    bgemm_wide<false, false, true><<<dim3(1, ROWS_Q / 128), 256>>>(
        g_ffnb, g_w2T, b2, g_src, g_ffn2, nullptr, ROWS_Q, 256, 1024);

    // 8. out = LN(ffn2sum)
    ln_kernel<<<ROWS_Q, 256>>>(g_ffn2, gamma2, beta2, out, nullptr);
}